// round 15
// baseline (speedup 1.0000x reference)
#include <cuda_runtime.h>
#include <cstdint>
#include <math.h>

// Problem constants
#define BB 4
#define NN 2048
#define EE 768
#define HH 8
#define DD 96
#define SCALING 0.1020620726159658f   // 96^-0.5

// Scratch (static device globals; no allocation). All tf32-pre-rounded.
// g_Q: d' = perm8(d)                      (uint2 Q frag loads)
// g_K: d'' = regroup(perm8(d))            (uint4 K frag loads, kc-pairs)
// g_V: plain [b][h][n][d]                 (transpose source)
// g_Vt: [b][h][d][smap(n)]                (uint4 V frag loads, kc-pairs)
__device__ float g_Q[BB * HH * NN * DD];
__device__ float g_K[BB * HH * NN * DD];
__device__ float g_V[BB * HH * NN * DD];
__device__ float g_Vt[BB * HH * DD * NN];
__device__ float g_ctx[BB * NN * EE];       // [b][n][e] plain
__device__ float g_xr[BB * NN * EE];        // rounded x (plain)
__device__ float g_Wqkvr[EE * 3 * EE];      // rounded Wqkv (plain)
__device__ float g_Wprojr[EE * EE];         // rounded Wproj (plain)

// ---------------------------------------------------------------------------
// helpers
// ---------------------------------------------------------------------------
__device__ __forceinline__ uint32_t tf32r(float x) {
    uint32_t y;
    asm("cvt.rna.tf32.f32 %0, %1;" : "=r"(y) : "f"(x));
    return y;
}

__device__ __forceinline__ int perm8(int k) {
    return (k & ~7) | (((k & 3) << 1) | ((k >> 2) & 1));
}
// regroup within 16: x = 8kc+2t+e -> 16(kc>>1) + 4t + 2(kc&1) + e
__device__ __forceinline__ int regroup16(int x) {
    return 16 * (x >> 4) + 4 * ((x >> 1) & 3) + 2 * ((x >> 3) & 1) + (x & 1);
}

__device__ __forceinline__ void mma_tf32(float* c, const uint32_t* a,
                                         const uint32_t* b) {
    asm volatile(
        "mma.sync.aligned.m16n8k8.row.col.f32.tf32.tf32.f32 "
        "{%0,%1,%2,%3}, {%4,%5,%6,%7}, {%8,%9}, {%0,%1,%2,%3};\n"
        : "+f"(c[0]), "+f"(c[1]), "+f"(c[2]), "+f"(c[3])
        : "r"(a[0]), "r"(a[1]), "r"(a[2]), "r"(a[3]), "r"(b[0]), "r"(b[1]));
}

__device__ __forceinline__ void mma_tf32_2(float* c, const uint32_t* a,
                                           uint32_t b0, uint32_t b1) {
    uint32_t bf[2] = { b0, b1 };
    mma_tf32(c, a, bf);
}

__device__ __forceinline__ void cp16(void* smem_ptr, const void* gptr) {
    uint32_t sa = (uint32_t)__cvta_generic_to_shared(smem_ptr);
    asm volatile("cp.async.cg.shared.global [%0], [%1], 16;"
                 :: "r"(sa), "l"(gptr));
}
#define CP_COMMIT() asm volatile("cp.async.commit_group;" ::: "memory")
#define CP_WAIT0()  asm volatile("cp.async.wait_group 0;" ::: "memory")

// ---------------------------------------------------------------------------
// Kernel 0: tf32-round ALL inputs in ONE launch. COUNTS IN FLOAT4 UNITS.
// ---------------------------------------------------------------------------
#define NX4 1572864     // x:     6291456 floats / 4
#define NW4 442368      // Wqkv:  1769472 floats / 4
#define NP4 147456      // Wproj:  589824 floats / 4

__global__ void round_all(const float4* __restrict__ sx,
                          const float4* __restrict__ sw,
                          const float4* __restrict__ sp)
{
    int i = blockIdx.x * blockDim.x + threadIdx.x;
    const float4* src;
    float4* dst;
    int j = i;
    if (j < NX4)              { src = sx; dst = (float4*)g_xr; }
    else if (j < NX4 + NW4)   { j -= NX4; src = sw; dst = (float4*)g_Wqkvr; }
    else if (j < NX4 + NW4 + NP4) { j -= NX4 + NW4; src = sp; dst = (float4*)g_Wprojr; }
    else return;
    float4 v = src[j];
    v.x = __uint_as_float(tf32r(v.x));
    v.y = __uint_as_float(tf32r(v.y));
    v.z = __uint_as_float(tf32r(v.z));
    v.w = __uint_as_float(tf32r(v.w));
    dst[j] = v;
}

// ---------------------------------------------------------------------------
// Kernel 0b: V transpose + key regroup. g_V[bh][n][d] -> g_Vt[bh][d][smap(n)]
// smap permutes within 16-key blocks: n -> (n&~15) | regroup16-local.
// ---------------------------------------------------------------------------
__global__ void transpose_v()
{
    __shared__ float tile[32][33];
    const int n0 = blockIdx.x * 32;
    const int d0 = blockIdx.y * 32;
    const int bh = blockIdx.z;
    const int tx = threadIdx.x, ty = threadIdx.y;

    #pragma unroll
    for (int j = 0; j < 4; j++)
        tile[ty + 8 * j][tx] = g_V[((size_t)bh * NN + n0 + ty + 8 * j) * DD + d0 + tx];
    __syncthreads();
    const int col = (tx & ~15) | (4 * ((tx >> 1) & 3) + 2 * ((tx >> 3) & 1) + (tx & 1));
    #pragma unroll
    for (int j = 0; j < 4; j++)
        g_Vt[((size_t)bh * DD + d0 + ty + 8 * j) * NN + n0 + col] = tile[tx][ty + 8 * j];
}

// ---------------------------------------------------------------------------
// Tensor-core tf32 GEMM (frozen R7/R9 shape): cp.async 2-stage.
// MODE 1 (qkv): scatter to g_Q (perm8 d), g_K (regroup(perm8) d), g_V plain.
// MODE 0 (proj): A=g_ctx, write fp32 out.
// ---------------------------------------------------------------------------
#define APAD 36
#define BPAD 136
#define ASZ (128 * APAD)
#define BSZ (32 * BPAD)
#define GSTG (ASZ + BSZ)
#define GSMEM (2 * GSTG * 4)

template<int MODE, int LDW>
__global__ __launch_bounds__(256, 2) void gemm_tc(
    const float* __restrict__ bias,
    float* __restrict__ out)
{
    extern __shared__ float sm[];
    const float* A = (MODE == 0) ? (const float*)g_ctx : (const float*)g_xr;
    const float* W = (MODE == 0) ? (const float*)g_Wprojr : (const float*)g_Wqkvr;

    const int tid  = threadIdx.x;
    const int lane = tid & 31;
    const int wid  = tid >> 5;
    const int wm   = wid & 3;
    const int wn   = wid >> 2;
    const int row0 = blockIdx.y * 128;
    const int col0 = blockIdx.x * 128;
    const int g    = lane >> 2;
    const int t    = lane & 3;

    float acc[2][8][4];
    #pragma unroll
    for (int ml = 0; ml < 2; ml++)
        #pragma unroll
        for (int nl = 0; nl < 8; nl++)
            #pragma unroll
            for (int e = 0; e < 4; e++) acc[ml][nl][e] = 0.f;

    auto issue = [&](int kt, int s) {
        float* sA = sm + s * GSTG;
        float* sB = sA + ASZ;
        #pragma unroll
        for (int p = 0; p < 4; p++) {
            int i = tid + p * 256;
            int m = i >> 3, k4 = i & 7;
            cp16(sA + m * APAD + k4 * 4,
                 A + (size_t)(row0 + m) * 768 + kt * 32 + k4 * 4);
        }
        #pragma unroll
        for (int p = 0; p < 4; p++) {
            int i = tid + p * 256;
            int k = i >> 5, n4 = i & 31;
            cp16(sB + k * BPAD + n4 * 4,
                 W + (size_t)(kt * 32 + k) * LDW + col0 + n4 * 4);
        }
        CP_COMMIT();
    };

    issue(0, 0);

    #pragma unroll 1
    for (int kt = 0; kt < 24; kt++) {
        const int s = kt & 1;
        CP_WAIT0();
        __syncthreads();
        if (kt < 23) issue(kt + 1, s ^ 1);

        const uint32_t* sA = (const uint32_t*)(sm + s * GSTG);
        const uint32_t* sB = sA + ASZ;

        #pragma unroll
        for (int ks = 0; ks < 4; ks++) {
            const int k0 = ks * 8;
            uint32_t af[2][4];
            #pragma unroll
            for (int ml = 0; ml < 2; ml++) {
                const int m_off = wm * 32 + ml * 16;
                af[ml][0] = sA[(m_off + g)     * APAD + k0 + t];
                af[ml][1] = sA[(m_off + g + 8) * APAD + k0 + t];
                af[ml][2] = sA[(m_off + g)     * APAD + k0 + t + 4];
                af[ml][3] = sA[(m_off + g + 8) * APAD + k0 + t + 4];
            }
            #pragma unroll
            for (int nl = 0; nl < 8; nl++) {
                const int n_off = wn * 64 + nl * 8;
                uint32_t bf[2];
                bf[0] = sB[(k0 + t)     * BPAD + n_off + g];
                bf[1] = sB[(k0 + t + 4) * BPAD + n_off + g];
                mma_tf32(acc[0][nl], af[0], bf);
                mma_tf32(acc[1][nl], af[1], bf);
            }
        }
    }

    // ---- epilogue ----
    if (MODE == 0) {
        #pragma unroll
        for (int ml = 0; ml < 2; ml++) {
            #pragma unroll
            for (int rh = 0; rh < 2; rh++) {
                int m = row0 + wm * 32 + ml * 16 + g + rh * 8;
                float* op = out + (size_t)m * LDW;
                #pragma unroll
                for (int nl = 0; nl < 8; nl++) {
                    int c = col0 + wn * 64 + nl * 8 + 2 * t;
                    float2 bv = *(const float2*)(bias + c);
                    float2 o;
                    o.x = acc[ml][nl][rh * 2 + 0] + bv.x;
                    o.y = acc[ml][nl][rh * 2 + 1] + bv.y;
                    *(float2*)(op + c) = o;
                }
            }
        }
    } else {
        #pragma unroll
        for (int ml = 0; ml < 2; ml++) {
            #pragma unroll
            for (int rh = 0; rh < 2; rh++) {
                int m = row0 + wm * 32 + ml * 16 + g + rh * 8;
                int b = m >> 11, n = m & 2047;
                #pragma unroll
                for (int nl = 0; nl < 8; nl++) {
                    #pragma unroll
                    for (int e = 0; e < 2; e++) {
                        int c = col0 + wn * 64 + nl * 8 + 2 * t + e;
                        float v = acc[ml][nl][rh * 2 + e] + __ldg(bias + c);
                        int sel = c % 3;
                        int hd  = c / 3;
                        int h   = hd / 96;
                        int d   = hd - h * 96;
                        float vr = __uint_as_float(tf32r(v));
                        size_t base = (size_t)(b * HH + h) * NN;
                        if (sel == 0)
                            g_Q[(base + n) * DD + perm8(d)] = vr;
                        else if (sel == 1)
                            g_K[(base + n) * DD + regroup16(perm8(d))] = vr;
                        else
                            g_V[(base + n) * DD + d] = vr;
                    }
                }
            }
        }
    }
}

// ---------------------------------------------------------------------------
// Flash attention, BN=128 keys/tile (16 tiles), 2-stage cp.async.
// BM=128 (8 warps x 16 rows -> warp-local softmax).
// K smem [128 keys][112 pad] d''-regrouped -> ONE uint4 per kc-PAIR.
// Vt smem [96 d][144 pad] key-smapped      -> ONE uint4 per kc-PAIR.
// S C-frags feed PV A-operand directly (smap encodes the required order).
// ---------------------------------------------------------------------------
#define BNK 128
#define KPAD 112
#define VPAD 144
#define KSZ (BNK * KPAD)            // 14336 floats
#define VSZ (DD * VPAD)             // 13824 floats
#define ASTG (KSZ + VSZ)            // 28160 floats per stage
#define ASMEM (2 * ASTG * 4)        // 225280 B

__global__ __launch_bounds__(256) void attn_mma()
{
    extern __shared__ float sm[];

    const int tid  = threadIdx.x;
    const int lane = tid & 31;
    const int wid  = tid >> 5;
    const int g    = lane >> 2;
    const int t    = lane & 3;
    const int q0   = blockIdx.x * 128;
    const int bh   = blockIdx.y;
    const int b    = bh >> 3;
    const int h    = bh & 7;

    const float* Qg  = g_Q  + (size_t)bh * NN * DD;
    const float* Kg  = g_K  + (size_t)bh * NN * DD;
    const float* Vtg = g_Vt + (size_t)bh * DD * NN;

    const int r0 = 16 * wid + g;
    const int r1 = r0 + 8;

    auto issueKV = [&](int kt, int s) {
        const int j0 = kt * BNK;
        float* bK = sm + s * ASTG;
        float* bV = bK + KSZ;
        #pragma unroll
        for (int p = 0; p < 12; p++) {          // K: 128 rows x 24 float4
            int i = tid + p * 256;
            int r = i / 24, c4 = i % 24;
            cp16(bK + r * KPAD + c4 * 4, Kg + (size_t)(j0 + r) * DD + c4 * 4);
        }
        #pragma unroll
        for (int p = 0; p < 12; p++) {          // Vt: 96 rows x 32 float4
            int i = tid + p * 256;
            int r = i >> 5, c4 = i & 31;
            cp16(bV + r * VPAD + c4 * 4, Vtg + (size_t)r * NN + j0 + c4 * 4);
        }
        CP_COMMIT();
    };

    issueKV(0, 0);

    uint32_t qf[12][4];
    {
        const uint32_t* Q0 = (const uint32_t*)(Qg + (size_t)(q0 + r0) * DD);
        const uint32_t* Q1 = (const uint32_t*)(Qg + (size_t)(q0 + r1) * DD);
        #pragma unroll
        for (int c = 0; c < 12; c++) {
            uint2 v0 = *(const uint2*)&Q0[8 * c + 2 * t];
            uint2 v1 = *(const uint2*)&Q1[8 * c + 2 * t];
            qf[c][0] = v0.x; qf[c][2] = v0.y;
            qf[c][1] = v1.x; qf[c][3] = v1.y;
        }
    }

    float m0 = -1e30f, m1 = -1e30f, l0 = 0.f, l1 = 0.f;
    float oacc[12][4];
    #pragma unroll
    for (int dc = 0; dc < 12; dc++)
        #pragma unroll
        for (int e = 0; e < 4; e++) oacc[dc][e] = 0.f;

    #pragma unroll 1
    for (int kt = 0; kt < NN / BNK; kt++) {
        const int s = kt & 1;
        CP_WAIT0();
        __syncthreads();
        if (kt < NN / BNK - 1) issueKV(kt + 1, s ^ 1);

        const uint32_t* sKu = (const uint32_t*)(sm + s * ASTG);
        const uint32_t* sVu = sKu + KSZ;

        // ---- S = Q K^T : 6 kc-pairs x 16 n-chunks, one uint4 per pair ----
        float sacc[16][4];
        #pragma unroll
        for (int nc = 0; nc < 16; nc++)
            #pragma unroll
            for (int e = 0; e < 4; e++) sacc[nc][e] = 0.f;

        #pragma unroll
        for (int P = 0; P < 6; P++) {
            #pragma unroll
            for (int nc = 0; nc < 16; nc++) {
                uint4 v = *(const uint4*)&sKu[(nc * 8 + g) * KPAD + P * 16 + 4 * t];
                mma_tf32_2(sacc[nc], qf[2 * P],     v.x, v.y);
                mma_tf32_2(sacc[nc], qf[2 * P + 1], v.z, v.w);
            }
        }

        // ---- online softmax (warp-local rows r0, r1) ----
        float lm0 = sacc[0][0], lm1 = sacc[0][2];
        #pragma unroll
        for (int nc = 0; nc < 16; nc++) {
            lm0 = fmaxf(lm0, fmaxf(sacc[nc][0], sacc[nc][1]));
            lm1 = fmaxf(lm1, fmaxf(sacc[nc][2], sacc[nc][3]));
        }
        lm0 = fmaxf(lm0, __shfl_xor_sync(0xffffffffu, lm0, 1));
        lm0 = fmaxf(lm0, __shfl_xor_sync(0xffffffffu, lm0, 2));
        lm1 = fmaxf(lm1, __shfl_xor_sync(0xffffffffu, lm1, 1));
        lm1 = fmaxf(lm1, __shfl_xor_sync(0xffffffffu, lm1, 2));

        const float mn0 = fmaxf(m0, lm0);
        const float mn1 = fmaxf(m1, lm1);
        const float sc0 = __expf(m0 - mn0);
        const float sc1 = __expf(m1 - mn1);
        m0 = mn0; m1 = mn1;

        float rs0 = 0.f, rs1 = 0.f;
        #pragma unroll
        for (int nc = 0; nc < 16; nc++) {
            sacc[nc][0] = __expf(sacc[nc][0] - mn0);
            sacc[nc][1] = __expf(sacc[nc][1] - mn0);
            sacc[nc][2] = __expf(sacc[nc][2] - mn1);
            sacc[nc][3] = __expf(sacc[nc][3] - mn1);
            rs0 += sacc[nc][0] + sacc[nc][1];
            rs1 += sacc[nc][2] + sacc[nc][3];
        }
        rs0 += __shfl_xor_sync(0xffffffffu, rs0, 1);
        rs0 += __shfl_xor_sync(0xffffffffu, rs0, 2);
        rs1 += __shfl_xor_sync(0xffffffffu, rs1, 1);
        rs1 += __shfl_xor_sync(0xffffffffu, rs1, 2);
        l0 = l0 * sc0 + rs0;
        l1 = l1 * sc1 + rs1;

        if (__any_sync(0xffffffffu, (sc0 != 1.f) || (sc1 != 1.f))) {
            #pragma unroll
            for (int dc = 0; dc < 12; dc++) {
                oacc[dc][0] *= sc0; oacc[dc][1] *= sc0;
                oacc[dc][2] *= sc1; oacc[dc][3] *= sc1;
            }
        }

        // ---- O += P @ V : 8 kc-pairs x 12 d-chunks, one uint4 per pair ----
        #pragma unroll
        for (int P = 0; P < 8; P++) {
            uint32_t afe[4], afo[4];
            afe[0] = tf32r(sacc[2 * P][0]);
            afe[1] = tf32r(sacc[2 * P][2]);
            afe[2] = tf32r(sacc[2 * P][1]);
            afe[3] = tf32r(sacc[2 * P][3]);
            afo[0] = tf32r(sacc[2 * P + 1][0]);
            afo[1] = tf32r(sacc[2 * P + 1][2]);
            afo[2] = tf32r(sacc[2 * P + 1][1]);
            afo[3] = tf32r(sacc[2 * P + 1][3]);
            #pragma unroll
            for (int dc = 0; dc < 12; dc++) {
                uint4 v = *(const uint4*)&sVu[(dc * 8 + g) * VPAD + P * 16 + 4 * t];
                mma_tf32_2(oacc[dc], afe, v.x, v.y);
                mma_tf32_2(oacc[dc], afo, v.z, v.w);
            }
        }
    }

    // ---- epilogue: ctx = tf32r((O / l) * SCALING), plain e layout ----
    const float inv0 = SCALING / l0;
    const float inv1 = SCALING / l1;
    float* dst0 = g_ctx + ((size_t)b * NN + (q0 + r0)) * EE + h * DD;
    float* dst1 = g_ctx + ((size_t)b * NN + (q0 + r1)) * EE + h * DD;
    #pragma unroll
    for (int dc = 0; dc < 12; dc++) {
        float2 o0, o1;
        o0.x = __uint_as_float(tf32r(oacc[dc][0] * inv0));
        o0.y = __uint_as_float(tf32r(oacc[dc][1] * inv0));
        o1.x = __uint_as_float(tf32r(oacc[dc][2] * inv1));
        o1.y = __uint_as_float(tf32r(oacc[dc][3] * inv1));
        *(float2*)(dst0 + dc * 8 + 2 * t) = o0;
        *(float2*)(dst1 + dc * 8 + 2 * t) = o1;
    }
}

// ---------------------------------------------------------------------------
extern "C" void kernel_launch(void* const* d_in, const int* in_sizes, int n_in,
                              void* d_out, int out_size)
{
    const float* x     = (const float*)d_in[0];
    const float* Wqkv  = (const float*)d_in[1];
    const float* bqkv  = (const float*)d_in[2];
    const float* Wproj = (const float*)d_in[3];
    const float* bproj = (const float*)d_in[4];
    float* out = (float*)d_out;

    cudaFuncSetAttribute(gemm_tc<1, 2304>,
                         cudaFuncAttributeMaxDynamicSharedMemorySize, GSMEM);
    cudaFuncSetAttribute(gemm_tc<0, 768>,
                         cudaFuncAttributeMaxDynamicSharedMemorySize, GSMEM);
    cudaFuncSetAttribute(attn_mma,
                         cudaFuncAttributeMaxDynamicSharedMemorySize, ASMEM);

    round_all<<<(NX4 + NW4 + NP4 + 255) / 256, 256>>>(
        (const float4*)x, (const float4*)Wqkv, (const float4*)Wproj);

    dim3 g1(2304 / 128, 8192 / 128);      // 18 x 64
    gemm_tc<1, 2304><<<g1, 256, GSMEM>>>(bqkv, nullptr);

    dim3 gt(NN / 32, DD / 32, BB * HH);   // 64 x 3 x 32
    transpose_v<<<gt, dim3(32, 8)>>>();

    dim3 g2(NN / 128, BB * HH);           // 16 x 32
    attn_mma<<<g2, 256, ASMEM>>>();

    dim3 g3(768 / 128, 8192 / 128);       // 6 x 64
    gemm_tc<0, 768><<<g3, 256, GSMEM>>>(bproj, out);
}

// round 16
// speedup vs baseline: 1.0057x; 1.0057x over previous
#include <cuda_runtime.h>
#include <cstdint>
#include <math.h>

// Problem constants
#define BB 4
#define NN 2048
#define EE 768
#define HH 8
#define DD 96
#define SCALING 0.1020620726159658f   // 96^-0.5

// Scratch (static device globals; no allocation). All tf32-pre-rounded.
// g_Q/g_K: within-8 d permutation d'=(d&3)*2+(d>>2)  (uint2 frag loads).
// g_V: KEY-ROW permutation n'=(n&~7)|invperm8(n&7) (shuffle-free PV).
__device__ float g_Q[BB * HH * NN * DD];    // [b][h][n][d'] perm d
__device__ float g_K[BB * HH * NN * DD];    // [b][h][n][d'] perm d
__device__ float g_V[BB * HH * NN * DD];    // [b][h][n'][d] perm rows
__device__ float g_ctx[BB * NN * EE];       // [b][n][e] plain
__device__ float g_xr[BB * NN * EE];        // rounded x (plain)
__device__ float g_Wqkvr[EE * 3 * EE];      // rounded Wqkv (plain)
__device__ float g_Wprojr[EE * EE];         // rounded Wproj (plain)

// ---------------------------------------------------------------------------
// helpers
// ---------------------------------------------------------------------------
__device__ __forceinline__ uint32_t tf32r(float x) {
    uint32_t y;
    asm("cvt.rna.tf32.f32 %0, %1;" : "=r"(y) : "f"(x));
    return y;
}

__device__ __forceinline__ int perm8(int k) {
    return (k & ~7) | (((k & 3) << 1) | ((k >> 2) & 1));
}
__device__ __forceinline__ int invperm8(int k) {
    return ((k & 1) << 2) | ((k >> 1) & 3);
}

__device__ __forceinline__ void mma_tf32(float* c, const uint32_t* a,
                                         const uint32_t* b) {
    asm volatile(
        "mma.sync.aligned.m16n8k8.row.col.f32.tf32.tf32.f32 "
        "{%0,%1,%2,%3}, {%4,%5,%6,%7}, {%8,%9}, {%0,%1,%2,%3};\n"
        : "+f"(c[0]), "+f"(c[1]), "+f"(c[2]), "+f"(c[3])
        : "r"(a[0]), "r"(a[1]), "r"(a[2]), "r"(a[3]), "r"(b[0]), "r"(b[1]));
}

__device__ __forceinline__ void cp16(void* smem_ptr, const void* gptr) {
    uint32_t sa = (uint32_t)__cvta_generic_to_shared(smem_ptr);
    asm volatile("cp.async.cg.shared.global [%0], [%1], 16;"
                 :: "r"(sa), "l"(gptr));
}
#define CP_COMMIT() asm volatile("cp.async.commit_group;" ::: "memory")
#define CP_WAIT0()  asm volatile("cp.async.wait_group 0;" ::: "memory")
#define CP_WAIT1()  asm volatile("cp.async.wait_group 1;" ::: "memory")

// ---------------------------------------------------------------------------
// Kernel 0: tf32-round ALL inputs in ONE launch. COUNTS IN FLOAT4 UNITS:
//   x:     4*2048*768 = 6291456 floats = 1572864 float4
//   Wqkv:  768*2304   = 1769472 floats =  442368 float4
//   Wproj: 768*768    =  589824 floats =  147456 float4
// ---------------------------------------------------------------------------
#define NX4 1572864
#define NW4 442368
#define NP4 147456

__global__ void round_all(const float4* __restrict__ sx,
                          const float4* __restrict__ sw,
                          const float4* __restrict__ sp)
{
    int i = blockIdx.x * blockDim.x + threadIdx.x;
    const float4* src;
    float4* dst;
    int j = i;
    if (j < NX4)              { src = sx; dst = (float4*)g_xr; }
    else if (j < NX4 + NW4)   { j -= NX4; src = sw; dst = (float4*)g_Wqkvr; }
    else if (j < NX4 + NW4 + NP4) { j -= NX4 + NW4; src = sp; dst = (float4*)g_Wprojr; }
    else return;
    float4 v = src[j];
    v.x = __uint_as_float(tf32r(v.x));
    v.y = __uint_as_float(tf32r(v.y));
    v.z = __uint_as_float(tf32r(v.z));
    v.w = __uint_as_float(tf32r(v.w));
    dst[j] = v;
}

// ---------------------------------------------------------------------------
// Tensor-core tf32 GEMM (frozen R7/R9 inner loop): cp.async THREE-stage.
// C[8192,LDW] = A[8192,768] @ W[768,LDW] + bias. Tile 128x128x32, 8 warps,
// warp tile 32x64, scalar fragment LDS.
// MODE 1 (qkv): scatter to g_Q/g_K (perm d), g_V (perm row n).
// MODE 0 (proj): A=g_ctx, write fp32 out.
// ---------------------------------------------------------------------------
#define APAD 36
#define BPAD 136
#define ASZ (128 * APAD)
#define BSZ (32 * BPAD)
#define GSTG (ASZ + BSZ)
#define NSTG 3
#define GSMEM (NSTG * GSTG * 4)      // 107520 B

template<int MODE, int LDW>
__global__ __launch_bounds__(256, 2) void gemm_tc(
    const float* __restrict__ bias,
    float* __restrict__ out)
{
    extern __shared__ float sm[];
    const float* A = (MODE == 0) ? (const float*)g_ctx : (const float*)g_xr;
    const float* W = (MODE == 0) ? (const float*)g_Wprojr : (const float*)g_Wqkvr;

    const int tid  = threadIdx.x;
    const int lane = tid & 31;
    const int wid  = tid >> 5;
    const int wm   = wid & 3;
    const int wn   = wid >> 2;
    const int row0 = blockIdx.y * 128;
    const int col0 = blockIdx.x * 128;
    const int g    = lane >> 2;
    const int t    = lane & 3;

    float acc[2][8][4];
    #pragma unroll
    for (int ml = 0; ml < 2; ml++)
        #pragma unroll
        for (int nl = 0; nl < 8; nl++)
            #pragma unroll
            for (int e = 0; e < 4; e++) acc[ml][nl][e] = 0.f;

    auto issue = [&](int kt, int s) {
        float* sA = sm + s * GSTG;
        float* sB = sA + ASZ;
        #pragma unroll
        for (int p = 0; p < 4; p++) {
            int i = tid + p * 256;
            int m = i >> 3, k4 = i & 7;
            cp16(sA + m * APAD + k4 * 4,
                 A + (size_t)(row0 + m) * 768 + kt * 32 + k4 * 4);
        }
        #pragma unroll
        for (int p = 0; p < 4; p++) {
            int i = tid + p * 256;
            int k = i >> 5, n4 = i & 31;
            cp16(sB + k * BPAD + n4 * 4,
                 W + (size_t)(kt * 32 + k) * LDW + col0 + n4 * 4);
        }
        CP_COMMIT();
    };

    issue(0, 0);
    issue(1, 1);

    #pragma unroll 1
    for (int kt = 0; kt < 24; kt++) {
        const int s = kt % 3;
        if (kt < 22) CP_WAIT1(); else CP_WAIT0();
        __syncthreads();
        if (kt < 22) issue(kt + 2, (kt + 2) % 3);

        const uint32_t* sA = (const uint32_t*)(sm + s * GSTG);
        const uint32_t* sB = sA + ASZ;

        #pragma unroll
        for (int ks = 0; ks < 4; ks++) {
            const int k0 = ks * 8;
            uint32_t af[2][4];
            #pragma unroll
            for (int ml = 0; ml < 2; ml++) {
                const int m_off = wm * 32 + ml * 16;
                af[ml][0] = sA[(m_off + g)     * APAD + k0 + t];
                af[ml][1] = sA[(m_off + g + 8) * APAD + k0 + t];
                af[ml][2] = sA[(m_off + g)     * APAD + k0 + t + 4];
                af[ml][3] = sA[(m_off + g + 8) * APAD + k0 + t + 4];
            }
            #pragma unroll
            for (int nl = 0; nl < 8; nl++) {
                const int n_off = wn * 64 + nl * 8;
                uint32_t bf[2];
                bf[0] = sB[(k0 + t)     * BPAD + n_off + g];
                bf[1] = sB[(k0 + t + 4) * BPAD + n_off + g];
                mma_tf32(acc[0][nl], af[0], bf);
                mma_tf32(acc[1][nl], af[1], bf);
            }
        }
    }

    // ---- epilogue ----
    if (MODE == 0) {
        #pragma unroll
        for (int ml = 0; ml < 2; ml++) {
            #pragma unroll
            for (int rh = 0; rh < 2; rh++) {
                int m = row0 + wm * 32 + ml * 16 + g + rh * 8;
                float* op = out + (size_t)m * LDW;
                #pragma unroll
                for (int nl = 0; nl < 8; nl++) {
                    int c = col0 + wn * 64 + nl * 8 + 2 * t;
                    float2 bv = *(const float2*)(bias + c);
                    float2 o;
                    o.x = acc[ml][nl][rh * 2 + 0] + bv.x;
                    o.y = acc[ml][nl][rh * 2 + 1] + bv.y;
                    *(float2*)(op + c) = o;
                }
            }
        }
    } else {
        #pragma unroll
        for (int ml = 0; ml < 2; ml++) {
            #pragma unroll
            for (int rh = 0; rh < 2; rh++) {
                int m = row0 + wm * 32 + ml * 16 + g + rh * 8;
                int b = m >> 11, n = m & 2047;
                int np = (n & ~7) | invperm8(n & 7);   // V row permutation
                #pragma unroll
                for (int nl = 0; nl < 8; nl++) {
                    #pragma unroll
                    for (int e = 0; e < 2; e++) {
                        int c = col0 + wn * 64 + nl * 8 + 2 * t + e;
                        float v = acc[ml][nl][rh * 2 + e] + __ldg(bias + c);
                        int sel = c % 3;
                        int hd  = c / 3;
                        int h   = hd / 96;
                        int d   = hd - h * 96;
                        float vr = __uint_as_float(tf32r(v));
                        size_t base = (size_t)(b * HH + h) * NN;
                        if (sel == 0)      g_Q[(base + n) * DD + perm8(d)] = vr;
                        else if (sel == 1) g_K[(base + n) * DD + perm8(d)] = vr;
                        else               g_V[(base + np) * DD + d]       = vr;
                    }
                }
            }
        }
    }
}

// ---------------------------------------------------------------------------
// Flash attention (R13 exact, validated 653.8us config): mma.sync tf32,
// BN=128 keys/tile (16 tiles), 2-stage cp.async. BM=128 (8 warps x 16 rows
// -> warp-local softmax). g_Q/g_K permuted d -> uint2 frags. g_V rows
// pre-permuted in gmem so S C-frags feed the PV A-operand directly.
// ---------------------------------------------------------------------------
#define BNK 128
#define KVPAD 104
#define KVSZ (BNK * KVPAD)          // 13312 floats
#define ASTG (2 * KVSZ)
#define ASMEM (2 * ASTG * 4)        // 212992 B

__global__ __launch_bounds__(256) void attn_mma()
{
    extern __shared__ float sm[];

    const int tid  = threadIdx.x;
    const int lane = tid & 31;
    const int wid  = tid >> 5;
    const int g    = lane >> 2;
    const int t    = lane & 3;
    const int q0   = blockIdx.x * 128;
    const int bh   = blockIdx.y;
    const int b    = bh >> 3;
    const int h    = bh & 7;

    const float* Qg = g_Q + (size_t)bh * NN * DD;
    const float* Kg = g_K + (size_t)bh * NN * DD;
    const float* Vg = g_V + (size_t)bh * NN * DD;

    const int r0 = 16 * wid + g;
    const int r1 = r0 + 8;

    auto issueKV = [&](int kt, int s) {
        const int j0 = kt * BNK;
        float* bK = sm + s * ASTG;
        float* bV = bK + KVSZ;
        #pragma unroll
        for (int p = 0; p < 12; p++) {
            int i  = tid + p * 256;              // 3072 float4s per tensor
            int r  = i / 24, c4 = i % 24;
            cp16(bK + r * KVPAD + c4 * 4, Kg + (size_t)(j0 + r) * DD + c4 * 4);
            cp16(bV + r * KVPAD + c4 * 4, Vg + (size_t)(j0 + r) * DD + c4 * 4);
        }
        CP_COMMIT();
    };

    issueKV(0, 0);

    uint32_t qf[12][4];
    {
        const uint32_t* Q0 = (const uint32_t*)(Qg + (size_t)(q0 + r0) * DD);
        const uint32_t* Q1 = (const uint32_t*)(Qg + (size_t)(q0 + r1) * DD);
        #pragma unroll
        for (int c = 0; c < 12; c++) {
            uint2 v0 = *(const uint2*)&Q0[8 * c + 2 * t];
            uint2 v1 = *(const uint2*)&Q1[8 * c + 2 * t];
            qf[c][0] = v0.x; qf[c][2] = v0.y;
            qf[c][1] = v1.x; qf[c][3] = v1.y;
        }
    }

    float m0 = -1e30f, m1 = -1e30f, l0 = 0.f, l1 = 0.f;
    float oacc[12][4];
    #pragma unroll
    for (int dc = 0; dc < 12; dc++)
        #pragma unroll
        for (int e = 0; e < 4; e++) oacc[dc][e] = 0.f;

    #pragma unroll 1
    for (int kt = 0; kt < NN / BNK; kt++) {
        const int s = kt & 1;
        CP_WAIT0();
        __syncthreads();
        if (kt < NN / BNK - 1) issueKV(kt + 1, s ^ 1);

        const uint32_t* sKu = (const uint32_t*)(sm + s * ASTG);
        const uint32_t* sVu = sKu + KVSZ;

        // ---- S = Q K^T : 16 n-chunks x 12 k-chunks ----
        float sacc[16][4];
        #pragma unroll
        for (int nc = 0; nc < 16; nc++)
            #pragma unroll
            for (int e = 0; e < 4; e++) sacc[nc][e] = 0.f;

        #pragma unroll
        for (int kc = 0; kc < 12; kc++) {
            #pragma unroll
            for (int nc = 0; nc < 16; nc++) {
                uint2 v = *(const uint2*)&sKu[(nc * 8 + g) * KVPAD + kc * 8 + 2 * t];
                uint32_t bf[2] = { v.x, v.y };
                mma_tf32(sacc[nc], qf[kc], bf);
            }
        }

        // ---- online softmax (warp-local rows r0, r1) ----
        float lm0 = sacc[0][0], lm1 = sacc[0][2];
        #pragma unroll
        for (int nc = 0; nc < 16; nc++) {
            lm0 = fmaxf(lm0, fmaxf(sacc[nc][0], sacc[nc][1]));
            lm1 = fmaxf(lm1, fmaxf(sacc[nc][2], sacc[nc][3]));
        }
        lm0 = fmaxf(lm0, __shfl_xor_sync(0xffffffffu, lm0, 1));
        lm0 = fmaxf(lm0, __shfl_xor_sync(0xffffffffu, lm0, 2));
        lm1 = fmaxf(lm1, __shfl_xor_sync(0xffffffffu, lm1, 1));
        lm1 = fmaxf(lm1, __shfl_xor_sync(0xffffffffu, lm1, 2));

        const float mn0 = fmaxf(m0, lm0);
        const float mn1 = fmaxf(m1, lm1);
        const float sc0 = __expf(m0 - mn0);
        const float sc1 = __expf(m1 - mn1);
        m0 = mn0; m1 = mn1;

        float rs0 = 0.f, rs1 = 0.f;
        #pragma unroll
        for (int nc = 0; nc < 16; nc++) {
            sacc[nc][0] = __expf(sacc[nc][0] - mn0);
            sacc[nc][1] = __expf(sacc[nc][1] - mn0);
            sacc[nc][2] = __expf(sacc[nc][2] - mn1);
            sacc[nc][3] = __expf(sacc[nc][3] - mn1);
            rs0 += sacc[nc][0] + sacc[nc][1];
            rs1 += sacc[nc][2] + sacc[nc][3];
        }
        rs0 += __shfl_xor_sync(0xffffffffu, rs0, 1);
        rs0 += __shfl_xor_sync(0xffffffffu, rs0, 2);
        rs1 += __shfl_xor_sync(0xffffffffu, rs1, 1);
        rs1 += __shfl_xor_sync(0xffffffffu, rs1, 2);
        l0 = l0 * sc0 + rs0;
        l1 = l1 * sc1 + rs1;

        if (__any_sync(0xffffffffu, (sc0 != 1.f) || (sc1 != 1.f))) {
            #pragma unroll
            for (int dc = 0; dc < 12; dc++) {
                oacc[dc][0] *= sc0; oacc[dc][1] *= sc0;
                oacc[dc][2] *= sc1; oacc[dc][3] *= sc1;
            }
        }

        // ---- O += P @ V : C-frags feed A directly (V rows pre-permuted) ----
        #pragma unroll
        for (int kc = 0; kc < 16; kc++) {
            uint32_t af[4];
            af[0] = tf32r(sacc[kc][0]);
            af[1] = tf32r(sacc[kc][2]);
            af[2] = tf32r(sacc[kc][1]);
            af[3] = tf32r(sacc[kc][3]);
            #pragma unroll
            for (int dc = 0; dc < 12; dc++) {
                uint32_t bf[2];
                bf[0] = sVu[(kc * 8 + t)     * KVPAD + dc * 8 + g];
                bf[1] = sVu[(kc * 8 + t + 4) * KVPAD + dc * 8 + g];
                mma_tf32(oacc[dc], af, bf);
            }
        }
    }

    // ---- epilogue: ctx = tf32r((O / l) * SCALING), plain e layout ----
    const float inv0 = SCALING / l0;
    const float inv1 = SCALING / l1;
    float* dst0 = g_ctx + ((size_t)b * NN + (q0 + r0)) * EE + h * DD;
    float* dst1 = g_ctx + ((size_t)b * NN + (q0 + r1)) * EE + h * DD;
    #pragma unroll
    for (int dc = 0; dc < 12; dc++) {
        float2 o0, o1;
        o0.x = __uint_as_float(tf32r(oacc[dc][0] * inv0));
        o0.y = __uint_as_float(tf32r(oacc[dc][1] * inv0));
        o1.x = __uint_as_float(tf32r(oacc[dc][2] * inv1));
        o1.y = __uint_as_float(tf32r(oacc[dc][3] * inv1));
        *(float2*)(dst0 + dc * 8 + 2 * t) = o0;
        *(float2*)(dst1 + dc * 8 + 2 * t) = o1;
    }
}

// ---------------------------------------------------------------------------
extern "C" void kernel_launch(void* const* d_in, const int* in_sizes, int n_in,
                              void* d_out, int out_size)
{
    const float* x     = (const float*)d_in[0];
    const float* Wqkv  = (const float*)d_in[1];
    const float* bqkv  = (const float*)d_in[2];
    const float* Wproj = (const float*)d_in[3];
    const float* bproj = (const float*)d_in[4];
    float* out = (float*)d_out;

    cudaFuncSetAttribute(gemm_tc<1, 2304>,
                         cudaFuncAttributeMaxDynamicSharedMemorySize, GSMEM);
    cudaFuncSetAttribute(gemm_tc<0, 768>,
                         cudaFuncAttributeMaxDynamicSharedMemorySize, GSMEM);
    cudaFuncSetAttribute(attn_mma,
                         cudaFuncAttributeMaxDynamicSharedMemorySize, ASMEM);

    // one launch rounds everything (counts are float4 units)
    round_all<<<(NX4 + NW4 + NP4 + 255) / 256, 256>>>(
        (const float4*)x, (const float4*)Wqkv, (const float4*)Wproj);

    dim3 g1(2304 / 128, 8192 / 128);      // 18 x 64
    gemm_tc<1, 2304><<<g1, 256, GSMEM>>>(bqkv, nullptr);

    dim3 g2(NN / 128, BB * HH);           // 16 x 32
    attn_mma<<<g2, 256, ASMEM>>>();

    dim3 g3(768 / 128, 8192 / 128);       // 6 x 64
    gemm_tc<0, 768><<<g3, 256, GSMEM>>>(bproj, out);
}